// round 14
// baseline (speedup 1.0000x reference)
#include <cuda_runtime.h>

#define N_PTS 65536
#define N_NODES 4096
#define KCH 24            // per-team chain length (guard band over 20)
#define KSD 20
#define IN_STRIDE 35
#define NBINS 4096
#define HALF_NODES 2048
#define TCHUNK 1024
#define SEEDW 64
#define FINF 3.0e38f

__device__ float4 g_nodes4s[N_NODES];     // Morton-sorted: (vx,vy,vz,|v|^2)
__device__ float4 g_rec_s[N_NODES * 4];   // sorted records: R, g+t, g
__device__ int g_binCount[NBINS], g_binCursor[NBINS], g_cellArr[N_PTS], g_perm[N_PTS];
__device__ int g_nBinCount[NBINS], g_nBinCursor[NBINS], g_nodeStart[NBINS];
__device__ int g_nCell[N_NODES], g_nPerm[N_NODES];

__device__ __forceinline__ unsigned expand3(unsigned v) {
    return (v & 1u) | ((v & 2u) << 2) | ((v & 4u) << 4) | ((v & 8u) << 6);
}
__device__ __forceinline__ int quant4(float x) {
    int q = (int)floorf((x + 3.0f) * (16.0f / 6.0f));
    return q < 0 ? 0 : (q > 15 ? 15 : q);
}
__device__ __forceinline__ unsigned morton3(float x, float y, float z) {
    return expand3(quant4(x)) | (expand3(quant4(y)) << 1) | (expand3(quant4(z)) << 2);
}

__global__ void zero_kernel() {
    int i = blockIdx.x * blockDim.x + threadIdx.x;
    if (i < NBINS) { g_binCount[i] = 0; g_nBinCount[i] = 0; }
}

__global__ void count_kernel(const float* __restrict__ inputs, const float* __restrict__ vd) {
    int idx = blockIdx.x * blockDim.x + threadIdx.x;
    if (idx < N_PTS) {
        const float* pr = inputs + (long)idx * IN_STRIDE;
        unsigned code = morton3(pr[0], pr[1], pr[2]);
        g_cellArr[idx] = (int)code;
        atomicAdd(&g_binCount[code], 1);
    }
    if (idx < N_NODES) {
        unsigned code = morton3(vd[idx*3+0], vd[idx*3+1], vd[idx*3+2]);
        g_nCell[idx] = (int)code;
        atomicAdd(&g_nBinCount[code], 1);
    }
}

__global__ void scan_kernel() {
    __shared__ int ssum[1024];
    int tid = threadIdx.x;
    const int* cntArr = (blockIdx.x == 0) ? g_binCount : g_nBinCount;
    int base = tid * 4;
    int c0 = cntArr[base], c1 = cntArr[base+1], c2 = cntArr[base+2], c3 = cntArr[base+3];
    ssum[tid] = c0 + c1 + c2 + c3;
    __syncthreads();
    for (int off = 1; off < 1024; off <<= 1) {
        int v = ssum[tid];
        int add = (tid >= off) ? ssum[tid - off] : 0;
        __syncthreads();
        ssum[tid] = v + add;
        __syncthreads();
    }
    int excl = (tid > 0) ? ssum[tid - 1] : 0;
    int e0 = excl, e1 = excl + c0, e2 = excl + c0 + c1, e3 = excl + c0 + c1 + c2;
    if (blockIdx.x == 0) {
        g_binCursor[base] = e0; g_binCursor[base+1] = e1;
        g_binCursor[base+2] = e2; g_binCursor[base+3] = e3;
    } else {
        g_nBinCursor[base] = e0; g_nBinCursor[base+1] = e1;
        g_nBinCursor[base+2] = e2; g_nBinCursor[base+3] = e3;
        g_nodeStart[base] = e0; g_nodeStart[base+1] = e1;
        g_nodeStart[base+2] = e2; g_nodeStart[base+3] = e3;
    }
}

__global__ void scatter_kernel() {
    int idx = blockIdx.x * blockDim.x + threadIdx.x;
    if (idx < N_PTS) {
        int pos = atomicAdd(&g_binCursor[g_cellArr[idx]], 1);
        g_perm[pos] = idx;
    }
    if (idx < N_NODES) {
        int pos = atomicAdd(&g_nBinCursor[g_nCell[idx]], 1);
        g_nPerm[pos] = idx;
    }
}

__global__ void build_sorted_kernel(const float* __restrict__ vd, const float* __restrict__ R,
                                    const float* __restrict__ g, const float* __restrict__ t) {
    int pos = blockIdx.x * blockDim.x + threadIdx.x;
    if (pos >= N_NODES) return;
    int j = g_nPerm[pos];
    float vx = vd[j*3+0], vy = vd[j*3+1], vz = vd[j*3+2];
    g_nodes4s[pos] = make_float4(vx, vy, vz, fmaf(vx,vx,fmaf(vy,vy,vz*vz)));
    const float* Rj = R + j*9;
    float g0 = g[j*3+0], g1 = g[j*3+1], g2 = g[j*3+2];
    float gt0 = g0 + t[j*3+0], gt1 = g1 + t[j*3+1], gt2 = g2 + t[j*3+2];
    g_rec_s[pos*4+0] = make_float4(Rj[0], Rj[1], Rj[2], Rj[3]);
    g_rec_s[pos*4+1] = make_float4(Rj[4], Rj[5], Rj[6], Rj[7]);
    g_rec_s[pos*4+2] = make_float4(Rj[8], gt0, gt1, gt2);
    g_rec_s[pos*4+3] = make_float4(g0, g1, g2, 0.0f);
}

__device__ __forceinline__ float pack_key(float s, int j) {
    return __uint_as_float((__float_as_uint(s) & 0xFFFFF000u) | (unsigned)j);
}

#define INSERT24(SV) do {                                              \
    _Pragma("unroll")                                                  \
    for (int _k = KCH-1; _k >= 1; --_k)                                \
        d[_k] = fminf(d[_k], fmaxf(d[_k-1], (SV)));                    \
    d[0] = fminf(d[0], (SV));                                          \
} while (0)

#define INSERT20(SV) do {                                              \
    _Pragma("unroll")                                                  \
    for (int _k = KSD-1; _k >= 1; --_k)                                \
        ds[_k] = fminf(ds[_k], fmaxf(ds[_k-1], (SV)));                 \
    ds[0] = fminf(ds[0], (SV));                                        \
} while (0)

// 256 threads = 2 teams x 128; both teams serve the SAME 128 points,
// team t sweeps node half [t*2048, (t+1)*2048).
__global__ void __launch_bounds__(256) dg_kernel(const float* __restrict__ inputs,
                                                 float* __restrict__ out) {
    __shared__ float4 snbuf[2 * TCHUNK];       // 32 KB; reused as s_mg after sweep
    __shared__ float  red[13 * 128];           // 6.7 KB team-1 partials

    const int tid  = threadIdx.x;
    const int team = tid >> 7;                 // 0 or 1
    const int wt   = tid & 127;                // within-team thread = point slot

    const int pt = g_perm[blockIdx.x * 128 + wt];
    const float* pr = inputs + (long)pt * IN_STRIDE;
    const float px = pr[0], py = pr[1], pz = pr[2];
    const float pp = fmaf(px, px, fmaf(py, py, pz * pz));
    const float qa = -2.0f * px, qb = -2.0f * py, qc = -2.0f * pz;

    // ---- seed (both teams compute identical theta; no cross-team wait) ----
    float ds[KSD];
    #pragma unroll
    for (int k = 0; k < KSD; k++) ds[k] = FINF;
    {
        int W0 = g_nodeStart[g_cellArr[pt]] - 22;
        if (W0 < 0) W0 = 0;
        if (W0 > N_NODES - SEEDW) W0 = N_NODES - SEEDW;
        #pragma unroll 4
        for (int i = 0; i < SEEDW; i++) {
            float4 v = __ldg(&g_nodes4s[W0 + i]);
            float s = fmaf(qa, v.x, fmaf(qb, v.y, fmaf(qc, v.z, v.w)));
            INSERT20(s);
        }
    }
    const float T0 = ds[KSD-1];
    const float theta = T0 + fabsf(T0) * 0.002f + 1e-5f;
    const unsigned thbits = __float_as_uint(theta);

    // ---- per-team sweep chain initialized to theta ----
    float d[KCH];
    #pragma unroll
    for (int k = 0; k < KCH; k++) d[k] = theta;

    const int nbase0 = team * HALF_NODES;
    float4* myChunk = snbuf + team * TCHUNK;

    for (int ch = 0; ch < HALF_NODES / TCHUNK; ch++) {
        const int base = nbase0 + ch * TCHUNK;
        __syncthreads();
        #pragma unroll
        for (int i = wt; i < TCHUNK; i += 128)
            myChunk[i] = g_nodes4s[base + i];
        __syncthreads();
        #pragma unroll 1
        for (int jj = 0; jj < TCHUNK; jj += 8) {
            float kk[8];
            #pragma unroll
            for (int u = 0; u < 8; u++) {
                float4 v = myChunk[jj + u];
                float s = fmaf(qa, v.x, fmaf(qb, v.y, fmaf(qc, v.z, v.w)));
                kk[u] = pack_key(s, base + jj + u);
            }
            float kmin = fminf(fminf(fminf(kk[0], kk[1]), fminf(kk[2], kk[3])),
                               fminf(fminf(kk[4], kk[5]), fminf(kk[6], kk[7])));
            if (__any_sync(0xffffffffu, kmin < d[KCH-1])) {
                #pragma unroll
                for (int u = 0; u < 8; u++) {
                    if (__any_sync(0xffffffffu, kk[u] < d[KCH-1])) INSERT24(kk[u]);
                }
            }
        }
    }

    // ---- publish exact s of own 24 entries (+ own smin) to smem ----
    __syncthreads();                            // chunks retired
    float* s_mg = (float*)snbuf;                // 25 rows x 256 cols = 25.6 KB

    float smin = FINF;
    #pragma unroll
    for (int k = 0; k < KCH; k++) {
        unsigned kb = __float_as_uint(d[k]);
        int j = (int)(kb & 0xFFFu);
        float4 v = __ldg(&g_nodes4s[j]);
        float s = fmaf(qa, v.x, fmaf(qb, v.y, fmaf(qc, v.z, v.w)));
        s = (kb == thbits) ? FINF : s;
        s_mg[k * 256 + tid] = s;
        smin = fminf(smin, s);
    }
    s_mg[24 * 256 + tid] = smin;
    __syncthreads();

    // ---- each thread: exact 20th of the 48-value union (identical per team pair) ----
    #pragma unroll
    for (int k = 0; k < KSD; k++) ds[k] = FINF;
    #pragma unroll 4
    for (int k = 0; k < KCH; k++) {
        INSERT20(s_mg[k * 256 + tid]);
        INSERT20(s_mg[k * 256 + (tid ^ 128)]);
    }
    const float T = ds[KSD-1];
    const float dis0 = fminf(smin, s_mg[24 * 256 + (tid ^ 128)]) + pp;
    const float dismax = T + pp;
    const float rcpmax = 1.0f / dismax;

    // ---- blend own 24 entries with s <= T ----
    float wsum = 0.0f, pb0 = 0.0f, pb1 = 0.0f, pb2 = 0.0f;
    float rb9[9];
    #pragma unroll
    for (int i = 0; i < 9; i++) rb9[i] = 0.0f;

    #pragma unroll 4
    for (int k = 0; k < KCH; k++) {
        float s = s_mg[k * 256 + tid];
        if (s <= T) {
            int j = (int)(__float_as_uint(d[k]) & 0xFFFu);
            float dis = s + pp;
            float uu = 1.0f - dis * rcpmax;
            float w = uu * uu;
            const float4* rec = g_rec_s + j * 4;
            float4 r0 = __ldg(rec + 0);
            float4 r1 = __ldg(rec + 1);
            float4 r2v = __ldg(rec + 2);
            float4 r3 = __ldg(rec + 3);
            float y0 = px - r2v.y, y1 = py - r2v.z, y2 = pz - r2v.w;
            float q0 = fmaf(r0.x, y0, fmaf(r0.w, y1, fmaf(r1.z, y2, r3.x)));
            float q1 = fmaf(r0.y, y0, fmaf(r1.x, y1, fmaf(r1.w, y2, r3.y)));
            float q2 = fmaf(r0.z, y0, fmaf(r1.y, y1, fmaf(r2v.x, y2, r3.z)));
            wsum += w;
            pb0 = fmaf(w, q0, pb0);
            pb1 = fmaf(w, q1, pb1);
            pb2 = fmaf(w, q2, pb2);
            rb9[0] = fmaf(w, r0.x, rb9[0]);
            rb9[1] = fmaf(w, r0.w, rb9[1]);
            rb9[2] = fmaf(w, r1.z, rb9[2]);
            rb9[3] = fmaf(w, r0.y, rb9[3]);
            rb9[4] = fmaf(w, r1.x, rb9[4]);
            rb9[5] = fmaf(w, r1.w, rb9[5]);
            rb9[6] = fmaf(w, r0.z, rb9[6]);
            rb9[7] = fmaf(w, r1.y, rb9[7]);
            rb9[8] = fmaf(w, r2v.x, rb9[8]);
        }
    }

    // ---- cross-team reduction: team 1 publishes, team 0 sums + writes ----
    __syncthreads();      // s_mg reads complete before any future reuse; blends done
    if (team == 1) {
        red[ 0 * 128 + wt] = wsum;
        red[ 1 * 128 + wt] = pb0;
        red[ 2 * 128 + wt] = pb1;
        red[ 3 * 128 + wt] = pb2;
        #pragma unroll
        for (int i = 0; i < 9; i++) red[(4 + i) * 128 + wt] = rb9[i];
    }
    __syncthreads();
    if (team == 0) {
        wsum += red[0 * 128 + wt];
        pb0  += red[1 * 128 + wt];
        pb1  += red[2 * 128 + wt];
        pb2  += red[3 * 128 + wt];
        #pragma unroll
        for (int i = 0; i < 9; i++) rb9[i] += red[(4 + i) * 128 + wt];

        const float inv = 1.0f / wsum;
        float o0 = (dis0 > 0.00021f) ? 1000000000.0f : pb0 * inv;
        float* op = out + (long)pt * 3;
        op[0] = o0;
        op[1] = pb1 * inv;
        op[2] = pb2 * inv;
        float* orr = out + (long)N_PTS * 3 + (long)pt * 9;
        #pragma unroll
        for (int i = 0; i < 9; i++) orr[i] = rb9[i] * inv;
    }
}

extern "C" void kernel_launch(void* const* d_in, const int* in_sizes, int n_in,
                              void* d_out, int out_size) {
    const float* inputs = (const float*)d_in[0];
    const float* vd     = (const float*)d_in[1];
    const float* R      = (const float*)d_in[2];
    const float* g      = (const float*)d_in[3];
    const float* t      = (const float*)d_in[4];
    float* out = (float*)d_out;

    zero_kernel<<<NBINS / 256, 256>>>();
    count_kernel<<<N_PTS / 256, 256>>>(inputs, vd);
    scan_kernel<<<2, 1024>>>();
    scatter_kernel<<<N_PTS / 256, 256>>>();
    build_sorted_kernel<<<N_NODES / 256, 256>>>(vd, R, g, t);
    dg_kernel<<<N_PTS / 128, 256>>>(inputs, out);
}

// round 15
// speedup vs baseline: 1.2683x; 1.2683x over previous
#include <cuda_runtime.h>

#define N_PTS 65536
#define N_NODES 4096
#define KCH 24            // sweep chain length (guard band over 20)
#define KSD 20
#define IN_STRIDE 35
#define NBINS 4096
#define CHUNK 2048
#define SEEDW 64
#define FINF 3.0e38f

__device__ float4 g_nodes4s[N_NODES];     // Morton-sorted: (vx,vy,vz,|v|^2)
__device__ float4 g_rec_s[N_NODES * 4];   // sorted records: R, g+t, g
__device__ float4 g_pts4[N_PTS];          // perm-ordered: (px,py,pz,pp)
__device__ int    g_w0arr[N_PTS];         // perm-ordered clamped seed window base
__device__ int g_binCount[NBINS], g_binCursor[NBINS], g_cellArr[N_PTS], g_perm[N_PTS];
__device__ int g_nBinCount[NBINS], g_nBinCursor[NBINS], g_nodeStart[NBINS];
__device__ int g_nCell[N_NODES], g_nPerm[N_NODES];

__device__ __forceinline__ unsigned expand3(unsigned v) {
    return (v & 1u) | ((v & 2u) << 2) | ((v & 4u) << 4) | ((v & 8u) << 6);
}
__device__ __forceinline__ int quant4(float x) {
    int q = (int)floorf((x + 3.0f) * (16.0f / 6.0f));
    return q < 0 ? 0 : (q > 15 ? 15 : q);
}
__device__ __forceinline__ unsigned morton3(float x, float y, float z) {
    return expand3(quant4(x)) | (expand3(quant4(y)) << 1) | (expand3(quant4(z)) << 2);
}

__global__ void zero_kernel() {
    int i = blockIdx.x * blockDim.x + threadIdx.x;
    if (i < NBINS) { g_binCount[i] = 0; g_nBinCount[i] = 0; }
}

__global__ void count_kernel(const float* __restrict__ inputs, const float* __restrict__ vd) {
    int idx = blockIdx.x * blockDim.x + threadIdx.x;
    if (idx < N_PTS) {
        const float* pr = inputs + (long)idx * IN_STRIDE;
        unsigned code = morton3(pr[0], pr[1], pr[2]);
        g_cellArr[idx] = (int)code;
        atomicAdd(&g_binCount[code], 1);
    }
    if (idx < N_NODES) {
        unsigned code = morton3(vd[idx*3+0], vd[idx*3+1], vd[idx*3+2]);
        g_nCell[idx] = (int)code;
        atomicAdd(&g_nBinCount[code], 1);
    }
}

__global__ void scan_kernel() {
    __shared__ int ssum[1024];
    int tid = threadIdx.x;
    const int* cntArr = (blockIdx.x == 0) ? g_binCount : g_nBinCount;
    int base = tid * 4;
    int c0 = cntArr[base], c1 = cntArr[base+1], c2 = cntArr[base+2], c3 = cntArr[base+3];
    ssum[tid] = c0 + c1 + c2 + c3;
    __syncthreads();
    for (int off = 1; off < 1024; off <<= 1) {
        int v = ssum[tid];
        int add = (tid >= off) ? ssum[tid - off] : 0;
        __syncthreads();
        ssum[tid] = v + add;
        __syncthreads();
    }
    int excl = (tid > 0) ? ssum[tid - 1] : 0;
    int e0 = excl, e1 = excl + c0, e2 = excl + c0 + c1, e3 = excl + c0 + c1 + c2;
    if (blockIdx.x == 0) {
        g_binCursor[base] = e0; g_binCursor[base+1] = e1;
        g_binCursor[base+2] = e2; g_binCursor[base+3] = e3;
    } else {
        g_nBinCursor[base] = e0; g_nBinCursor[base+1] = e1;
        g_nBinCursor[base+2] = e2; g_nBinCursor[base+3] = e3;
        g_nodeStart[base] = e0; g_nodeStart[base+1] = e1;
        g_nodeStart[base+2] = e2; g_nodeStart[base+3] = e3;
    }
}

// scatter points (writing packed point records) and nodes
__global__ void scatter_kernel(const float* __restrict__ inputs) {
    int idx = blockIdx.x * blockDim.x + threadIdx.x;
    if (idx < N_PTS) {
        int cell = g_cellArr[idx];
        int pos = atomicAdd(&g_binCursor[cell], 1);
        g_perm[pos] = idx;
        const float* pr = inputs + (long)idx * IN_STRIDE;
        float px = pr[0], py = pr[1], pz = pr[2];
        g_pts4[pos] = make_float4(px, py, pz, fmaf(px, px, fmaf(py, py, pz * pz)));
        int W0 = g_nodeStart[cell] - 22;
        if (W0 < 0) W0 = 0;
        if (W0 > N_NODES - SEEDW) W0 = N_NODES - SEEDW;
        g_w0arr[pos] = W0;
    }
    if (idx < N_NODES) {
        int pos = atomicAdd(&g_nBinCursor[g_nCell[idx]], 1);
        g_nPerm[pos] = idx;
    }
}

__global__ void build_sorted_kernel(const float* __restrict__ vd, const float* __restrict__ R,
                                    const float* __restrict__ g, const float* __restrict__ t) {
    int pos = blockIdx.x * blockDim.x + threadIdx.x;
    if (pos >= N_NODES) return;
    int j = g_nPerm[pos];
    float vx = vd[j*3+0], vy = vd[j*3+1], vz = vd[j*3+2];
    g_nodes4s[pos] = make_float4(vx, vy, vz, fmaf(vx,vx,fmaf(vy,vy,vz*vz)));
    const float* Rj = R + j*9;
    float g0 = g[j*3+0], g1 = g[j*3+1], g2 = g[j*3+2];
    float gt0 = g0 + t[j*3+0], gt1 = g1 + t[j*3+1], gt2 = g2 + t[j*3+2];
    g_rec_s[pos*4+0] = make_float4(Rj[0], Rj[1], Rj[2], Rj[3]);
    g_rec_s[pos*4+1] = make_float4(Rj[4], Rj[5], Rj[6], Rj[7]);
    g_rec_s[pos*4+2] = make_float4(Rj[8], gt0, gt1, gt2);
    g_rec_s[pos*4+3] = make_float4(g0, g1, g2, 0.0f);
}

__device__ __forceinline__ float pack_key(float s, int j) {
    return __uint_as_float((__float_as_uint(s) & 0xFFFFF000u) | (unsigned)j);
}

#define INSERT24(SV) do {                                              \
    _Pragma("unroll")                                                  \
    for (int _k = KCH-1; _k >= 1; --_k)                                \
        d[_k] = fminf(d[_k], fmaxf(d[_k-1], (SV)));                    \
    d[0] = fminf(d[0], (SV));                                          \
} while (0)

#define INSERT20(SV) do {                                              \
    _Pragma("unroll")                                                  \
    for (int _k = KSD-1; _k >= 1; --_k)                                \
        ds[_k] = fminf(ds[_k], fmaxf(ds[_k-1], (SV)));                 \
    ds[0] = fminf(ds[0], (SV));                                        \
} while (0)

__global__ void __launch_bounds__(128) dg_kernel(float* __restrict__ out) {
    __shared__ float4 sn[CHUNK];   // 32 KB

    const int tid = threadIdx.x;
    const int gpos = blockIdx.x * 128 + tid;
    const int pt = g_perm[gpos];
    const float4 p4 = g_pts4[gpos];
    const float px = p4.x, py = p4.y, pz = p4.z, pp = p4.w;
    const float qa = -2.0f * px, qb = -2.0f * py, qc = -2.0f * pz;

    // ---- per-lane seed: unconditional 20-chain over own 64-node Morton window ----
    float ds[KSD];
    #pragma unroll
    for (int k = 0; k < KSD; k++) ds[k] = FINF;
    {
        const int W0 = g_w0arr[gpos];
        #pragma unroll 4
        for (int i = 0; i < SEEDW; i++) {
            float4 v = __ldg(&g_nodes4s[W0 + i]);
            float s = fmaf(qa, v.x, fmaf(qb, v.y, fmaf(qc, v.z, v.w)));
            INSERT20(s);
        }
    }
    const float T0 = ds[KSD-1];
    const float theta = T0 + fabsf(T0) * 0.002f + 1e-5f;
    const unsigned thbits = __float_as_uint(theta);

    // ---- sweep chain initialized to theta ----
    float d[KCH];
    #pragma unroll
    for (int k = 0; k < KCH; k++) d[k] = theta;
    // raw-s fire threshold: key(s) >= s - |s|*2^-11 >= s - 0.07 for |s| <= ~140
    float dthr = d[KCH-1] + 0.07f;

    // ---- single sweep, batch-8: raw-s min + conservative vote; exact keys on fire ----
    for (int ch = 0; ch < N_NODES / CHUNK; ch++) {
        const int base = ch * CHUNK;
        __syncthreads();
        #pragma unroll
        for (int i = tid; i < CHUNK; i += 128)
            sn[i] = g_nodes4s[base + i];
        __syncthreads();
        #pragma unroll 1
        for (int jj = 0; jj < CHUNK; jj += 8) {
            float sv[8];
            #pragma unroll
            for (int u = 0; u < 8; u++) {
                float4 v = sn[jj + u];
                sv[u] = fmaf(qa, v.x, fmaf(qb, v.y, fmaf(qc, v.z, v.w)));
            }
            float smin = fminf(fminf(fminf(sv[0], sv[1]), fminf(sv[2], sv[3])),
                               fminf(fminf(sv[4], sv[5]), fminf(sv[6], sv[7])));
            if (__any_sync(0xffffffffu, smin < dthr)) {
                #pragma unroll
                for (int u = 0; u < 8; u++) {
                    float key = pack_key(sv[u], base + jj + u);
                    if (__any_sync(0xffffffffu, key < d[KCH-1])) INSERT24(key);
                }
                dthr = d[KCH-1] + 0.07f;
            }
        }
    }

    // ---- exact re-selection: padding entries (== theta) act as +INF ----
    float m0 = -FINF, m1 = -FINF, m2 = -FINF, m3 = -FINF, m4 = -FINF;
    float smin2 = FINF;
    #pragma unroll
    for (int k = 0; k < KCH; k++) {
        unsigned kb = __float_as_uint(d[k]);
        int j = (int)(kb & 0xFFFu);
        float4 v = __ldg(&g_nodes4s[j]);
        float s = fmaf(qa, v.x, fmaf(qb, v.y, fmaf(qc, v.z, v.w)));
        s = (kb == thbits) ? FINF : s;
        smin2 = fminf(smin2, s);
        m4 = fmaxf(m4, fminf(m3, s));
        m3 = fmaxf(m3, fminf(m2, s));
        m2 = fmaxf(m2, fminf(m1, s));
        m1 = fmaxf(m1, fminf(m0, s));
        m0 = fmaxf(m0, s);
    }
    const float T = m4;
    const float dis0 = smin2 + pp;
    const float dismax = T + pp;
    const float rcpmax = 1.0f / dismax;

    // ---- blend over chain entries with s <= T (padding s = INF auto-excluded) ----
    float wsum = 0.0f, pb0 = 0.0f, pb1 = 0.0f, pb2 = 0.0f;
    float rb9[9];
    #pragma unroll
    for (int i = 0; i < 9; i++) rb9[i] = 0.0f;

    #pragma unroll 4
    for (int k = 0; k < KCH; k++) {
        unsigned kb = __float_as_uint(d[k]);
        int j = (int)(kb & 0xFFFu);
        float4 v = __ldg(&g_nodes4s[j]);
        float s = fmaf(qa, v.x, fmaf(qb, v.y, fmaf(qc, v.z, v.w)));
        s = (kb == thbits) ? FINF : s;
        if (s <= T) {
            float dis = s + pp;
            float uu = 1.0f - dis * rcpmax;
            float w = uu * uu;
            const float4* rec = g_rec_s + j * 4;
            float4 r0 = __ldg(rec + 0);
            float4 r1 = __ldg(rec + 1);
            float4 r2v = __ldg(rec + 2);
            float4 r3 = __ldg(rec + 3);
            float y0 = px - r2v.y, y1 = py - r2v.z, y2 = pz - r2v.w;
            float q0 = fmaf(r0.x, y0, fmaf(r0.w, y1, fmaf(r1.z, y2, r3.x)));
            float q1 = fmaf(r0.y, y0, fmaf(r1.x, y1, fmaf(r1.w, y2, r3.y)));
            float q2 = fmaf(r0.z, y0, fmaf(r1.y, y1, fmaf(r2v.x, y2, r3.z)));
            wsum += w;
            pb0 = fmaf(w, q0, pb0);
            pb1 = fmaf(w, q1, pb1);
            pb2 = fmaf(w, q2, pb2);
            rb9[0] = fmaf(w, r0.x, rb9[0]);
            rb9[1] = fmaf(w, r0.w, rb9[1]);
            rb9[2] = fmaf(w, r1.z, rb9[2]);
            rb9[3] = fmaf(w, r0.y, rb9[3]);
            rb9[4] = fmaf(w, r1.x, rb9[4]);
            rb9[5] = fmaf(w, r1.w, rb9[5]);
            rb9[6] = fmaf(w, r0.z, rb9[6]);
            rb9[7] = fmaf(w, r1.y, rb9[7]);
            rb9[8] = fmaf(w, r2v.x, rb9[8]);
        }
    }

    const float inv = 1.0f / wsum;
    float o0 = (dis0 > 0.00021f) ? 1000000000.0f : pb0 * inv;
    float* op = out + (long)pt * 3;
    op[0] = o0;
    op[1] = pb1 * inv;
    op[2] = pb2 * inv;
    float* orr = out + (long)N_PTS * 3 + (long)pt * 9;
    #pragma unroll
    for (int i = 0; i < 9; i++) orr[i] = rb9[i] * inv;
}

extern "C" void kernel_launch(void* const* d_in, const int* in_sizes, int n_in,
                              void* d_out, int out_size) {
    const float* inputs = (const float*)d_in[0];
    const float* vd     = (const float*)d_in[1];
    const float* R      = (const float*)d_in[2];
    const float* g      = (const float*)d_in[3];
    const float* t      = (const float*)d_in[4];
    float* out = (float*)d_out;

    zero_kernel<<<NBINS / 256, 256>>>();
    count_kernel<<<N_PTS / 256, 256>>>(inputs, vd);
    scan_kernel<<<2, 1024>>>();
    scatter_kernel<<<N_PTS / 256, 256>>>(inputs);
    build_sorted_kernel<<<N_NODES / 256, 256>>>(vd, R, g, t);
    dg_kernel<<<N_PTS / 128, 128>>>(out);
}